// round 1
// baseline (speedup 1.0000x reference)
#include <cuda_runtime.h>
#include <cuda_bf16.h>

#define BDIM 256
#define NROWS 4096
#define DCOLS 8192

__device__ float g_partials[NROWS];

__device__ __forceinline__ float smoothl1(float a, float b) {
    float d = a - b;
    float ad = fabsf(d);
    // absd < 1 ? 0.5*d*d : absd - 0.5
    return (ad < 1.0f) ? (0.5f * d * d) : (ad - 0.5f);
}

__global__ __launch_bounds__(BDIM)
void mask_smoothl1_row_kernel(const float* __restrict__ in,
                              const float* __restrict__ tgt,
                              const int* __restrict__ mask,
                              float* __restrict__ partials) {
    const int row = blockIdx.x;
    const int m = mask[row];
    if (m == 0) {
        if (threadIdx.x == 0) partials[row] = 0.0f;
        return;
    }

    const float4* __restrict__ a =
        reinterpret_cast<const float4*>(in  + (size_t)row * DCOLS);
    const float4* __restrict__ b =
        reinterpret_cast<const float4*>(tgt + (size_t)row * DCOLS);

    // D/4 = 2048 float4 per row, 256 threads -> 8 iterations
    float acc = 0.0f;
    #pragma unroll
    for (int it = 0; it < (DCOLS / 4) / BDIM; ++it) {
        int i = it * BDIM + threadIdx.x;
        float4 x = a[i];
        float4 y = b[i];
        acc += smoothl1(x.x, y.x);
        acc += smoothl1(x.y, y.y);
        acc += smoothl1(x.z, y.z);
        acc += smoothl1(x.w, y.w);
    }

    // warp reduce
    #pragma unroll
    for (int off = 16; off > 0; off >>= 1)
        acc += __shfl_xor_sync(0xFFFFFFFFu, acc, off);

    __shared__ float warp_sums[BDIM / 32];
    const int wid = threadIdx.x >> 5;
    const int lid = threadIdx.x & 31;
    if (lid == 0) warp_sums[wid] = acc;
    __syncthreads();

    if (wid == 0) {
        float v = (lid < BDIM / 32) ? warp_sums[lid] : 0.0f;
        #pragma unroll
        for (int off = 4; off > 0; off >>= 1)
            v += __shfl_xor_sync(0xFFFFFFFFu, v, off);
        if (lid == 0)
            partials[row] = v * ((float)m / (float)DCOLS);
    }
}

__global__ __launch_bounds__(512)
void final_reduce_kernel(const float* __restrict__ partials,
                         float* __restrict__ out) {
    float acc = 0.0f;
    for (int i = threadIdx.x; i < NROWS; i += 512)
        acc += partials[i];

    #pragma unroll
    for (int off = 16; off > 0; off >>= 1)
        acc += __shfl_xor_sync(0xFFFFFFFFu, acc, off);

    __shared__ float warp_sums[16];
    const int wid = threadIdx.x >> 5;
    const int lid = threadIdx.x & 31;
    if (lid == 0) warp_sums[wid] = acc;
    __syncthreads();

    if (wid == 0) {
        float v = (lid < 16) ? warp_sums[lid] : 0.0f;
        #pragma unroll
        for (int off = 8; off > 0; off >>= 1)
            v += __shfl_xor_sync(0xFFFFFFFFu, v, off);
        if (lid == 0) out[0] = v;
    }
}

extern "C" void kernel_launch(void* const* d_in, const int* in_sizes, int n_in,
                              void* d_out, int out_size) {
    const float* inputs  = (const float*)d_in[0];
    const float* targets = (const float*)d_in[1];
    const int*   mask    = (const int*)d_in[2];
    float* out = (float*)d_out;

    float* partials;
    cudaGetSymbolAddress((void**)&partials, g_partials);

    mask_smoothl1_row_kernel<<<NROWS, BDIM>>>(inputs, targets, mask, partials);
    final_reduce_kernel<<<1, 512>>>(partials, out);
}